// round 1
// baseline (speedup 1.0000x reference)
#include <cuda_runtime.h>
#include <math.h>

#define NUM_CLASSES 10
#define Hh 480
#define Ww 640
#define SKIP 8
#define GY 60            // 480/8
#define GX 80            // 640/8
#define P  4800          // GY*GX
#define NMAX 8
#define EPSF 1e-6f
#define INLIER 0.9f

// ---------------- device scratch (no allocations allowed) ----------------
static __device__ int   g_lab[NMAX][P];
static __device__ float g_u[NMAX][P];
static __device__ float g_v[NMAX][P];
static __device__ float g_d[NMAX][P];

// class-sorted (stable, classes 1..9 packed contiguously)
static __device__ float g_su[NMAX][P];
static __device__ float g_sv[NMAX][P];
static __device__ float g_sd[NMAX][P];
static __device__ float g_sx[NMAX][P];
static __device__ float g_sy[NMAX][P];
static __device__ int   g_segStart[NMAX][11];   // segStart[k]..segStart[k+1] for class k (1..9); [0..1] empty
static __device__ float g_counts[NMAX][10];

static __device__ float g_hough[NMAX][10][P];
static __device__ float g_dsum[NMAX][10][P];

// ---------------- kernel 1: per-pixel prep + deterministic counting sort ----------------
// one block per batch, 320 threads = 10 warps (warp w owns class w)
__global__ void hv_prep_kernel(const int* __restrict__ label,
                               const float* __restrict__ vp)
{
    const int n   = blockIdx.x;
    const int tid = threadIdx.x;

    const int*   lab2d = label + (size_t)n * Hh * Ww;
    const float* vpn   = vp + (size_t)n * Hh * Ww * (3 * NUM_CLASSES);

    // phase 0: per-pixel values
    for (int p = tid; p < P; p += blockDim.x) {
        int iy = p / GX, ix = p - iy * GX;
        int y = iy * SKIP, x = ix * SKIP;
        int l = lab2d[y * Ww + x];
        const float* v3 = vpn + (size_t)(y * Ww + x) * (3 * NUM_CLASSES) + 3 * l;
        float u = v3[0];
        float v = v3[1];
        float w = v3[2];
        float nrm = sqrtf(u * u + v * v) + EPSF;
        g_lab[n][p] = l;
        g_u[n][p] = u / nrm;
        g_v[n][p] = v / nrm;
        g_d[n][p] = expf(fminf(fmaxf(w, -3.0f), 3.0f));
    }
    __syncthreads();

    const int w    = tid >> 5;
    const int lane = tid & 31;

    __shared__ int s_cnt[10];
    __shared__ int s_seg[11];

    // count per class (warp w counts class w)
    int c = 0;
    for (int base = 0; base < P; base += 32) {
        int l = g_lab[n][base + lane];
        unsigned m = __ballot_sync(0xffffffffu, l == w);
        c += __popc(m);
    }
    if (lane == 0) s_cnt[w] = c;
    __syncthreads();

    if (tid == 0) {
        s_seg[0] = 0;
        s_seg[1] = 0;                 // class 0 excluded from sorted arrays
        for (int k = 1; k < 10; k++) s_seg[k + 1] = s_seg[k] + s_cnt[k];
        for (int k = 0; k < 11; k++) g_segStart[n][k] = s_seg[k];
        for (int k = 0; k < 10; k++) g_counts[n][k] = (float)s_cnt[k];
    }
    __syncthreads();

    // stable scatter (pixel-index order preserved within class)
    if (w >= 1) {
        int off = s_seg[w];
        for (int base = 0; base < P; base += 32) {
            int p = base + lane;
            int l = g_lab[n][p];
            unsigned m = __ballot_sync(0xffffffffu, l == w);
            if (l == w) {
                int pos = off + __popc(m & ((1u << lane) - 1u));
                g_su[n][pos] = g_u[n][p];
                g_sv[n][pos] = g_v[n][p];
                g_sd[n][pos] = g_d[n][p];
                int iy = p / GX, ix = p - iy * GX;
                g_sx[n][pos] = (float)(ix * SKIP);
                g_sy[n][pos] = (float)(iy * SKIP);
            }
            off += __popc(m);
        }
    }
}

// ---------------- kernel 2: O(P^2) voting, class-segmented ----------------
#define VTILE 512
#define VBLK  128
__global__ void hv_vote_kernel()
{
    const int n = blockIdx.z;
    const int k = blockIdx.y + 1;               // class 1..9
    const int c = blockIdx.x * VBLK + threadIdx.x;

    __shared__ float sx[VTILE], sy[VTILE], su[VTILE], sv[VTILE], sd[VTILE];

    const int beg = g_segStart[n][k];
    const int end = g_segStart[n][k + 1];

    float fcx = 0.f, fcy = 0.f;
    if (c < P) {
        int iy = c / GX, ix = c - iy * GX;
        fcx = (float)(ix * SKIP);
        fcy = (float)(iy * SKIP);
    }

    float cnt = 0.0f, ds = 0.0f;

    for (int base = beg; base < end; base += VTILE) {
        int m = end - base;
        if (m > VTILE) m = VTILE;
        for (int j = threadIdx.x; j < m; j += VBLK) {
            sx[j] = g_sx[n][base + j];
            sy[j] = g_sy[n][base + j];
            su[j] = g_su[n][base + j];
            sv[j] = g_sv[n][base + j];
            sd[j] = g_sd[n][base + j];
        }
        __syncthreads();
        if (c < P) {
            #pragma unroll 4
            for (int j = 0; j < m; j++) {
                float dx = fcx - sx[j];
                float dy = fcy - sy[j];
                float rd = sqrtf(dx * dx + dy * dy) + EPSF;
                float dt = (su[j] * dx + sv[j] * dy) / rd;
                if (dt > INLIER) { cnt += 1.0f; ds += sd[j]; }
            }
        }
        __syncthreads();
    }

    if (c < P) {
        g_hough[n][k][c] = cnt;
        g_dsum[n][k][c]  = ds;
    }
}

// ---------------- kernel 3: zero the output buffer ----------------
__global__ void hv_zero_kernel(float* __restrict__ out, int sz)
{
    int i = blockIdx.x * blockDim.x + threadIdx.x;
    if (i < sz) out[i] = 0.0f;
}

// ---------------- kernel 4: argmax (first-max tie-break) + epilogue ----------------
__global__ void hv_final_kernel(const float* __restrict__ extents,
                                const float* __restrict__ meta,
                                float* __restrict__ out, int N)
{
    const int k = blockIdx.x + 1;     // class 1..9
    const int n = blockIdx.y;
    const int tid = threadIdx.x;      // 256 threads

    float bestv = -1.0f;
    int   besti = P;
    for (int c = tid; c < P; c += 256) {
        float v = g_hough[n][k][c];
        if (v > bestv || (v == bestv && c < besti)) { bestv = v; besti = c; }
    }

    __shared__ float rv[256];
    __shared__ int   ri[256];
    rv[tid] = bestv; ri[tid] = besti;
    __syncthreads();
    for (int s = 128; s > 0; s >>= 1) {
        if (tid < s) {
            float ov = rv[tid + s]; int oi = ri[tid + s];
            if (ov > rv[tid] || (ov == rv[tid] && oi < ri[tid])) { rv[tid] = ov; ri[tid] = oi; }
        }
        __syncthreads();
    }

    if (tid == 0) {
        float votes = rv[0];
        int   best  = ri[0];
        float davg  = g_dsum[n][k][best] / fmaxf(votes, 1.0f);
        int iy = best / GX, ix = best - iy * GX;
        float cx = (float)(ix * SKIP);
        float cy = (float)(iy * SKIP);
        float cntk = g_counts[n][k];

        bool valid = (votes > 20.0f) && (votes > 0.1f * cntk)
                     && (cntk * (float)(SKIP * SKIP) > 500.0f);

        const float* mt = meta + (size_t)n * 9;
        float fx = mt[0], fy = mt[4], ppx = mt[2], ppy = mt[5];

        float e0 = extents[k * 3 + 0];
        float e1 = extents[k * 3 + 1];
        float e2 = extents[k * 3 + 2];
        float diam = sqrtf(e0 * e0 + e1 * e1 + e2 * e2) + EPSF;

        float hx = 0.5f * diam * fx / fmaxf(davg, EPSF);
        float hy = 0.5f * diam * fy / fmaxf(davg, EPSF);
        float score = valid ? votes : 0.0f;

        const int Kd = NUM_CLASSES - 1;
        // output layout: box[N,Kd,7] | pose[N,Kd,7] | target[N,Kd,40] | weight[N,Kd,40] | domain[N,Kd]
        float* box = out + ((size_t)n * Kd + (k - 1)) * 7;
        box[0] = (float)n;
        box[1] = (float)k;
        box[2] = cx - hx;
        box[3] = cy - hy;
        box[4] = cx + hx;
        box[5] = cy + hy;
        box[6] = score;

        float* pose = out + (size_t)N * Kd * 7 + ((size_t)n * Kd + (k - 1)) * 7;
        pose[0] = 1.0f; pose[1] = 0.0f; pose[2] = 0.0f; pose[3] = 0.0f;
        pose[4] = (cx - ppx) * davg / fx;
        pose[5] = (cy - ppy) * davg / fy;
        pose[6] = davg;

        out[(size_t)N * Kd * 94 + (size_t)n * Kd + (k - 1)] = (float)n;  // domain
    }
}

// ---------------- launch ----------------
extern "C" void kernel_launch(void* const* d_in, const int* in_sizes, int n_in,
                              void* d_out, int out_size)
{
    const int*   label   = (const int*)d_in[0];
    const float* vp      = (const float*)d_in[1];
    const float* extents = (const float*)d_in[2];
    // d_in[3] = poses (unused by the computed outputs)
    const float* meta    = (const float*)d_in[4];
    float* out = (float*)d_out;

    int N = in_sizes[4] / 9;
    if (N < 1) N = 1;
    if (N > NMAX) N = NMAX;

    hv_prep_kernel<<<N, 320>>>(label, vp);

    dim3 gv((P + VBLK - 1) / VBLK, NUM_CLASSES - 1, N);
    hv_vote_kernel<<<gv, VBLK>>>();

    hv_zero_kernel<<<(out_size + 255) / 256, 256>>>(out, out_size);

    dim3 gf(NUM_CLASSES - 1, N);
    hv_final_kernel<<<gf, 256>>>(extents, meta, out, N);
}

// round 3
// speedup vs baseline: 1.1874x; 1.1874x over previous
#include <cuda_runtime.h>
#include <math.h>

#define NUM_CLASSES 10
#define Hh 480
#define Ww 640
#define SKIP 8
#define GY 60            // 480/8
#define GX 80            // 640/8
#define P  4800          // GY*GX
#define NMAX 8
#define EPSF 1e-6f
#define INLIER 0.9f
#define VTILE 512
#define VBLK  128

// ---------------- device scratch (no allocations allowed) ----------------
static __device__ int    g_lab[NMAX][P];
static __device__ float  g_u[NMAX][P];
static __device__ float  g_v[NMAX][P];
static __device__ float  g_d[NMAX][P];

// class-sorted (stable, classes 1..9 packed contiguously)
static __device__ float4 g_sxyuv[NMAX][P];     // (x, y, u, v)
static __device__ float  g_sd[NMAX][P];
static __device__ int    g_segStart[NMAX][11];
static __device__ float  g_counts[NMAX][10];

static __device__ float    g_dsum[NMAX][10][P];
static __device__ unsigned g_bestkey[NMAX][10];   // (cnt<<13)|(8191-c)

// ---------------- kernel 1: per-pixel prep (multi-block) ----------------
__global__ void hv_prep_kernel(const int* __restrict__ label,
                               const float* __restrict__ vp)
{
    const int n = blockIdx.y;
    const int p = blockIdx.x * blockDim.x + threadIdx.x;

    if (blockIdx.x == 0 && threadIdx.x < 10)
        g_bestkey[n][threadIdx.x] = 0u;

    if (p >= P) return;

    const int*   lab2d = label + (size_t)n * Hh * Ww;
    const float* vpn   = vp + (size_t)n * Hh * Ww * (3 * NUM_CLASSES);

    int iy = p / GX, ix = p - iy * GX;
    int y = iy * SKIP, x = ix * SKIP;
    int l = lab2d[y * Ww + x];
    const float* v3 = vpn + (size_t)(y * Ww + x) * (3 * NUM_CLASSES) + 3 * l;
    float u = v3[0];
    float v = v3[1];
    float w = v3[2];
    float nrm = sqrtf(u * u + v * v) + EPSF;
    g_lab[n][p] = l;
    g_u[n][p] = u / nrm;
    g_v[n][p] = v / nrm;
    g_d[n][p] = expf(fminf(fmaxf(w, -3.0f), 3.0f));
}

// ---------------- kernel 2: deterministic counting sort (1 block/n) ----------------
// 320 threads = 10 warps; warp w owns class w
__global__ void hv_sort_kernel()
{
    const int n   = blockIdx.x;
    const int tid = threadIdx.x;
    const int w    = tid >> 5;
    const int lane = tid & 31;

    __shared__ int s_cnt[10];
    __shared__ int s_seg[11];

    // count per class
    int c = 0;
    for (int base = 0; base < P; base += 32) {
        int l = g_lab[n][base + lane];
        unsigned m = __ballot_sync(0xffffffffu, l == w);
        c += __popc(m);
    }
    if (lane == 0) s_cnt[w] = c;
    __syncthreads();

    if (tid == 0) {
        s_seg[0] = 0;
        s_seg[1] = 0;                 // class 0 excluded from sorted arrays
        for (int k = 1; k < 10; k++) s_seg[k + 1] = s_seg[k] + s_cnt[k];
        for (int k = 0; k < 11; k++) g_segStart[n][k] = s_seg[k];
        for (int k = 0; k < 10; k++) g_counts[n][k] = (float)s_cnt[k];
    }
    __syncthreads();

    // stable scatter (pixel-index order preserved within class)
    if (w >= 1) {
        int off = s_seg[w];
        for (int base = 0; base < P; base += 32) {
            int p = base + lane;
            int l = g_lab[n][p];
            unsigned m = __ballot_sync(0xffffffffu, l == w);
            if (l == w) {
                int pos = off + __popc(m & ((1u << lane) - 1u));
                int iy = p / GX, ix = p - iy * GX;
                float4 t;
                t.x = (float)(ix * SKIP);
                t.y = (float)(iy * SKIP);
                t.z = g_u[n][p];
                t.w = g_v[n][p];
                g_sxyuv[n][pos] = t;
                g_sd[n][pos]    = g_d[n][p];
            }
            off += __popc(m);
        }
    }
}

// ---------------- kernel 3: O(P^2) voting + fused per-class argmax ----------------
__global__ void hv_vote_kernel()
{
    const int n = blockIdx.z;
    const int k = blockIdx.y + 1;               // class 1..9
    const int c = blockIdx.x * VBLK + threadIdx.x;

    __shared__ float4  sxy[VTILE];
    __shared__ float   sdd[VTILE];
    __shared__ unsigned skey[VBLK];

    const int beg = g_segStart[n][k];
    const int end = g_segStart[n][k + 1];

    float fcx = 0.f, fcy = 0.f;
    if (c < P) {
        int iy = c / GX, ix = c - iy * GX;
        fcx = (float)(ix * SKIP);
        fcy = (float)(iy * SKIP);
    }

    float cnt = 0.0f, ds = 0.0f;

    for (int base = beg; base < end; base += VTILE) {
        int m = end - base;
        if (m > VTILE) m = VTILE;
        for (int j = threadIdx.x; j < m; j += VBLK) {
            sxy[j] = g_sxyuv[n][base + j];
            sdd[j] = g_sd[n][base + j];
        }
        __syncthreads();
        if (c < P) {
            #pragma unroll 4
            for (int j = 0; j < m; j++) {
                float4 t = sxy[j];
                float dx = fcx - t.x;
                float dy = fcy - t.y;
                float s   = fmaf(dx, dx, dy * dy);
                float dot = fmaf(t.z, dx, t.w * dy);
                float dta = dot * rsqrtf(s);     // approx path (MUFU.RSQ)
                float diff = dta - INLIER;
                bool inl;
                if (fabsf(diff) < 1.5e-4f) {
                    // exact IEEE path (bitwise-identical to reference formula)
                    float rd = sqrtf(s) + EPSF;
                    inl = (dot / rd) > INLIER;
                } else {
                    inl = diff > 0.0f;   // NaN (s==0 -> dta NaN) lands here as false, matching exact
                }
                if (inl) { cnt += 1.0f; ds += sdd[j]; }
            }
        }
        __syncthreads();
    }

    unsigned key = 0u;
    if (c < P) {
        g_dsum[n][k][c] = ds;
        key = (((unsigned)cnt) << 13) | (unsigned)(8191 - c);
    }

    // block-wide max-key reduction, then one atomic per block
    skey[threadIdx.x] = key;
    __syncthreads();
    for (int s = VBLK / 2; s > 0; s >>= 1) {
        if (threadIdx.x < s) {
            unsigned o = skey[threadIdx.x + s];
            if (o > skey[threadIdx.x]) skey[threadIdx.x] = o;
        }
        __syncthreads();
    }
    if (threadIdx.x == 0)
        atomicMax(&g_bestkey[n][k], skey[0]);
}

// ---------------- kernel 4: zero train-only outputs + epilogue (1 block/n) ----------------
__global__ void hv_final_kernel(const float* __restrict__ extents,
                                const float* __restrict__ meta,
                                float* __restrict__ out, int N)
{
    const int n   = blockIdx.x;
    const int tid = threadIdx.x;
    const int Kd  = NUM_CLASSES - 1;

    float* box  = out + ((size_t)n * Kd) * 7;
    float* pose = out + (size_t)N * Kd * 7  + ((size_t)n * Kd) * 7;
    float* targ = out + (size_t)N * Kd * 14 + ((size_t)n * Kd) * 40;
    float* wgt  = out + (size_t)N * Kd * 54 + ((size_t)n * Kd) * 40;
    float* dom  = out + (size_t)N * Kd * 94 + (size_t)n * Kd;

    // zero target/weight slices for this n (box/pose/domain are fully overwritten)
    for (int i = tid; i < Kd * 40; i += blockDim.x) { targ[i] = 0.0f; wgt[i] = 0.0f; }
    __syncthreads();

    if (tid < Kd) {
        const int k = tid + 1;
        unsigned key = g_bestkey[n][k];
        float votes = (float)(key >> 13);
        int   best  = 8191 - (int)(key & 8191u);

        float davg = g_dsum[n][k][best] / fmaxf(votes, 1.0f);
        int iy = best / GX, ix = best - iy * GX;
        float cx = (float)(ix * SKIP);
        float cy = (float)(iy * SKIP);
        float cntk = g_counts[n][k];

        bool valid = (votes > 20.0f) && (votes > 0.1f * cntk)
                     && (cntk * (float)(SKIP * SKIP) > 500.0f);

        const float* mt = meta + (size_t)n * 9;
        float fx = mt[0], fy = mt[4], ppx = mt[2], ppy = mt[5];

        float e0 = extents[k * 3 + 0];
        float e1 = extents[k * 3 + 1];
        float e2 = extents[k * 3 + 2];
        float diam = sqrtf(e0 * e0 + e1 * e1 + e2 * e2) + EPSF;

        float hx = 0.5f * diam * fx / fmaxf(davg, EPSF);
        float hy = 0.5f * diam * fy / fmaxf(davg, EPSF);
        float score = valid ? votes : 0.0f;

        float* b = box + (k - 1) * 7;
        b[0] = (float)n;
        b[1] = (float)k;
        b[2] = cx - hx;
        b[3] = cy - hy;
        b[4] = cx + hx;
        b[5] = cy + hy;
        b[6] = score;

        float* ps = pose + (k - 1) * 7;
        ps[0] = 1.0f; ps[1] = 0.0f; ps[2] = 0.0f; ps[3] = 0.0f;
        ps[4] = (cx - ppx) * davg / fx;
        ps[5] = (cy - ppy) * davg / fy;
        ps[6] = davg;

        dom[k - 1] = (float)n;
    }
}

// ---------------- launch ----------------
extern "C" void kernel_launch(void* const* d_in, const int* in_sizes, int n_in,
                              void* d_out, int out_size)
{
    const int*   label   = (const int*)d_in[0];
    const float* vp      = (const float*)d_in[1];
    const float* extents = (const float*)d_in[2];
    // d_in[3] = poses (unused)
    const float* meta    = (const float*)d_in[4];
    float* out = (float*)d_out;

    int N = in_sizes[4] / 9;
    if (N < 1) N = 1;
    if (N > NMAX) N = NMAX;

    dim3 ga((P + 255) / 256, N);
    hv_prep_kernel<<<ga, 256>>>(label, vp);

    hv_sort_kernel<<<N, 320>>>();

    dim3 gv((P + VBLK - 1) / VBLK, NUM_CLASSES - 1, N);
    hv_vote_kernel<<<gv, VBLK>>>();

    hv_final_kernel<<<N, 256>>>(extents, meta, out, N);
}

// round 4
// speedup vs baseline: 1.7942x; 1.5111x over previous
#include <cuda_runtime.h>
#include <math.h>

#define NUM_CLASSES 10
#define Hh 480
#define Ww 640
#define SKIP 8
#define GY 60
#define GX 80
#define P  4800
#define NMAX 8
#define EPSF 1e-6f
#define INLIER 0.9f
#define VTILE 512
#define VBLK  128
#define CPT   2
#define VOTE_BX ((P + VBLK*CPT - 1) / (VBLK*CPT))     // 19
#define KD (NUM_CLASSES - 1)

// ---------------- device scratch ----------------
static __device__ float    g_u[NMAX][P];
static __device__ float    g_v[NMAX][P];
static __device__ float    g_d[NMAX][P];
static __device__ float4   g_sxyuv[NMAX][P];     // class-sorted (x,y,u,v)
static __device__ float    g_sd[NMAX][P];
static __device__ int      g_segStart[NMAX][11];
static __device__ float    g_counts[NMAX][10];
static __device__ float    g_dsum[NMAX][10][P];
static __device__ unsigned g_bestkey[NMAX][10];  // (cnt<<13)|(8191-c)
static __device__ unsigned g_done[NMAX];

// ================= kernel 1: fused prep + two-level counting sort =================
// grid = N blocks, 1024 threads (32 warps = 32 chunks of 150 pixels)
__global__ void __launch_bounds__(1024, 1)
hv_prep_sort_kernel(const int* __restrict__ label,
                    const float* __restrict__ vp,
                    float* __restrict__ out, int N)
{
    const int n    = blockIdx.x;
    const int tid  = threadIdx.x;
    const int warp = tid >> 5;
    const int lane = tid & 31;
    const unsigned FULL = 0xffffffffu;

    __shared__ int s_lab[P];          // 19.2 KB
    __shared__ int s_cnt[32][10];
    __shared__ int s_off[32][10];

    // reset bookkeeping + zero train-only output slices for this n
    if (tid < 10) g_bestkey[n][tid] = 0u;
    if (tid == 10) g_done[n] = 0u;
    {
        float* targ = out + (size_t)N * KD * 14 + (size_t)n * KD * 40;
        float* wgt  = out + (size_t)N * KD * 54 + (size_t)n * KD * 40;
        for (int i = tid; i < KD * 40; i += 1024) { targ[i] = 0.0f; wgt[i] = 0.0f; }
    }

    // phase A: stage labels in smem
    const int* lab2d = label + (size_t)n * Hh * Ww;
    for (int p = tid; p < P; p += 1024) {
        int iy = p / GX, ix = p - iy * GX;
        s_lab[p] = lab2d[iy * SKIP * Ww + ix * SKIP];
    }
    __syncthreads();

    // phase B: per-pixel u,v,d -> global (coalesced stores; read back after syncs)
    const float* vpn = vp + (size_t)n * Hh * Ww * (3 * NUM_CLASSES);
    for (int p = tid; p < P; p += 1024) {
        int iy = p / GX, ix = p - iy * GX;
        int l = s_lab[p];
        const float* v3 = vpn + (size_t)(iy * SKIP * Ww + ix * SKIP) * (3 * NUM_CLASSES) + 3 * l;
        float u = v3[0], v = v3[1], w = v3[2];
        float nrm = sqrtf(u * u + v * v) + EPSF;
        g_u[n][p] = u / nrm;
        g_v[n][p] = v / nrm;
        g_d[n][p] = expf(fminf(fmaxf(w, -3.0f), 3.0f));
    }

    // phase C1: per-chunk per-class counts (warp = chunk of 150 pixels)
    int cnt[10];
    #pragma unroll
    for (int k = 0; k < 10; k++) cnt[k] = 0;
    const int cbase = warp * 150;
    #pragma unroll
    for (int s = 0; s < 5; s++) {
        int o = s * 32 + lane;
        int l = (o < 150) ? s_lab[cbase + o] : -1;
        #pragma unroll
        for (int k = 0; k < 10; k++) {
            unsigned m = __ballot_sync(FULL, l == k);
            cnt[k] += __popc(m);
        }
    }
    if (lane == 0) {
        #pragma unroll
        for (int k = 0; k < 10; k++) s_cnt[warp][k] = cnt[k];
    }
    __syncthreads();   // also makes phase-B global writes block-visible

    // phase C2: warp 0 — shfl-scan chunk offsets + segment starts
    if (warp == 0) {
        int segrun = 0;
        if (lane == 0) { g_segStart[n][0] = 0; }
        #pragma unroll
        for (int k = 0; k < 10; k++) {
            int v = s_cnt[lane][k];
            int incl = v;
            #pragma unroll
            for (int d = 1; d < 32; d <<= 1) {
                int t = __shfl_up_sync(FULL, incl, d);
                if (lane >= d) incl += t;
            }
            int excl  = incl - v;
            int total = __shfl_sync(FULL, incl, 31);
            if (k >= 1) {
                s_off[lane][k] = segrun + excl;
                if (lane == 0) g_segStart[n][k] = segrun;
                segrun += total;
            }
            if (lane == 0) g_counts[n][k] = (float)total;
        }
        if (lane == 0) g_segStart[n][10] = segrun;
    }
    __syncthreads();

    // phase C3: parallel stable scatter (warp = chunk)
    int off[10];
    #pragma unroll
    for (int k = 1; k < 10; k++) off[k] = s_off[warp][k];
    #pragma unroll
    for (int s = 0; s < 5; s++) {
        int o = s * 32 + lane;
        int j = cbase + o;
        bool valid = (o < 150);
        int l = valid ? s_lab[j] : -1;
        float u = 0.f, v = 0.f, d = 0.f, x = 0.f, y = 0.f;
        if (valid && l > 0) {
            u = g_u[n][j]; v = g_v[n][j]; d = g_d[n][j];
            int iy = j / GX, ix = j - iy * GX;
            x = (float)(ix * SKIP);
            y = (float)(iy * SKIP);
        }
        #pragma unroll
        for (int k = 1; k < 10; k++) {
            unsigned m = __ballot_sync(FULL, l == k);
            if (l == k) {
                int pos = off[k] + __popc(m & ((1u << lane) - 1u));
                g_sxyuv[n][pos] = make_float4(x, y, u, v);
                g_sd[n][pos]    = d;
            }
            off[k] += __popc(m);
        }
    }
}

// ================= kernel 2: voting + fused argmax + last-block epilogue =================
__global__ void hv_vote_kernel(const float* __restrict__ extents,
                               const float* __restrict__ meta,
                               float* __restrict__ out, int N)
{
    const int n = blockIdx.z;
    const int k = blockIdx.y + 1;
    const int c0 = blockIdx.x * (VBLK * CPT) + threadIdx.x;
    const int c1 = c0 + VBLK;

    __shared__ float4   sxy[VTILE];
    __shared__ float    sdd[VTILE];
    __shared__ unsigned skey[VBLK];
    __shared__ int      s_last;

    const int beg = g_segStart[n][k];
    const int end = g_segStart[n][k + 1];

    float fcx0 = 0.f, fcy0 = 0.f, fcx1 = 0.f, fcy1 = 0.f;
    if (c0 < P) { int iy = c0 / GX, ix = c0 - iy * GX; fcx0 = (float)(ix * SKIP); fcy0 = (float)(iy * SKIP); }
    if (c1 < P) { int iy = c1 / GX, ix = c1 - iy * GX; fcx1 = (float)(ix * SKIP); fcy1 = (float)(iy * SKIP); }

    float cnt0 = 0.f, ds0 = 0.f, cnt1 = 0.f, ds1 = 0.f;

    for (int base = beg; base < end; base += VTILE) {
        int m = end - base;
        if (m > VTILE) m = VTILE;
        for (int j = threadIdx.x; j < m; j += VBLK) {
            sxy[j] = g_sxyuv[n][base + j];
            sdd[j] = g_sd[n][base + j];
        }
        __syncthreads();
        #pragma unroll 2
        for (int j = 0; j < m; j++) {
            float4 t = sxy[j];
            float dj = sdd[j];
            // candidate 0
            {
                float dx = fcx0 - t.x, dy = fcy0 - t.y;
                float s   = fmaf(dx, dx, dy * dy);
                float dot = fmaf(t.z, dx, t.w * dy);
                float dta = dot * rsqrtf(s);
                float diff = dta - INLIER;
                bool inl;
                if (fabsf(diff) < 1.5e-4f) {
                    float rd = sqrtf(s) + EPSF;
                    inl = (dot / rd) > INLIER;
                } else inl = diff > 0.0f;
                if (inl) { cnt0 += 1.0f; ds0 += dj; }
            }
            // candidate 1
            {
                float dx = fcx1 - t.x, dy = fcy1 - t.y;
                float s   = fmaf(dx, dx, dy * dy);
                float dot = fmaf(t.z, dx, t.w * dy);
                float dta = dot * rsqrtf(s);
                float diff = dta - INLIER;
                bool inl;
                if (fabsf(diff) < 1.5e-4f) {
                    float rd = sqrtf(s) + EPSF;
                    inl = (dot / rd) > INLIER;
                } else inl = diff > 0.0f;
                if (inl) { cnt1 += 1.0f; ds1 += dj; }
            }
        }
        __syncthreads();
    }

    unsigned key = 0u;
    if (c0 < P) {
        g_dsum[n][k][c0] = ds0;
        key = (((unsigned)cnt0) << 13) | (unsigned)(8191 - c0);
    }
    if (c1 < P) {
        g_dsum[n][k][c1] = ds1;
        unsigned key1 = (((unsigned)cnt1) << 13) | (unsigned)(8191 - c1);
        if (key1 > key) key = key1;
    }

    skey[threadIdx.x] = key;
    __syncthreads();
    for (int s = VBLK / 2; s > 0; s >>= 1) {
        if (threadIdx.x < s) {
            unsigned o = skey[threadIdx.x + s];
            if (o > skey[threadIdx.x]) skey[threadIdx.x] = o;
        }
        __syncthreads();
    }
    if (threadIdx.x == 0) {
        atomicMax(&g_bestkey[n][k], skey[0]);
        __threadfence();
        unsigned t = atomicAdd(&g_done[n], 1u);
        s_last = (t == (unsigned)(VOTE_BX * KD - 1)) ? 1 : 0;
    }
    __syncthreads();

    // last block of this n: epilogue
    if (s_last && threadIdx.x < KD) {
        __threadfence();
        const int kk = threadIdx.x + 1;
        unsigned bkey = g_bestkey[n][kk];
        float votes = (float)(bkey >> 13);
        int   best  = 8191 - (int)(bkey & 8191u);

        float davg = g_dsum[n][kk][best] / fmaxf(votes, 1.0f);
        int iy = best / GX, ix = best - iy * GX;
        float cx = (float)(ix * SKIP);
        float cy = (float)(iy * SKIP);
        float cntk = g_counts[n][kk];

        bool valid = (votes > 20.0f) && (votes > 0.1f * cntk)
                     && (cntk * (float)(SKIP * SKIP) > 500.0f);

        const float* mt = meta + (size_t)n * 9;
        float fx = mt[0], fy = mt[4], ppx = mt[2], ppy = mt[5];

        float e0 = extents[kk * 3 + 0];
        float e1 = extents[kk * 3 + 1];
        float e2 = extents[kk * 3 + 2];
        float diam = sqrtf(e0 * e0 + e1 * e1 + e2 * e2) + EPSF;

        float hx = 0.5f * diam * fx / fmaxf(davg, EPSF);
        float hy = 0.5f * diam * fy / fmaxf(davg, EPSF);
        float score = valid ? votes : 0.0f;

        float* b = out + ((size_t)n * KD + (kk - 1)) * 7;
        b[0] = (float)n;
        b[1] = (float)kk;
        b[2] = cx - hx;
        b[3] = cy - hy;
        b[4] = cx + hx;
        b[5] = cy + hy;
        b[6] = score;

        float* ps = out + (size_t)N * KD * 7 + ((size_t)n * KD + (kk - 1)) * 7;
        ps[0] = 1.0f; ps[1] = 0.0f; ps[2] = 0.0f; ps[3] = 0.0f;
        ps[4] = (cx - ppx) * davg / fx;
        ps[5] = (cy - ppy) * davg / fy;
        ps[6] = davg;

        out[(size_t)N * KD * 94 + (size_t)n * KD + (kk - 1)] = (float)n;
    }
}

// ---------------- launch ----------------
extern "C" void kernel_launch(void* const* d_in, const int* in_sizes, int n_in,
                              void* d_out, int out_size)
{
    const int*   label   = (const int*)d_in[0];
    const float* vp      = (const float*)d_in[1];
    const float* extents = (const float*)d_in[2];
    const float* meta    = (const float*)d_in[4];
    float* out = (float*)d_out;

    int N = in_sizes[4] / 9;
    if (N < 1) N = 1;
    if (N > NMAX) N = NMAX;

    hv_prep_sort_kernel<<<N, 1024>>>(label, vp, out, N);

    dim3 gv(VOTE_BX, KD, N);
    hv_vote_kernel<<<gv, VBLK>>>(extents, meta, out, N);
}

// round 5
// speedup vs baseline: 3.4171x; 1.9045x over previous
#include <cuda_runtime.h>
#include <math.h>

#define NUM_CLASSES 10
#define Hh 480
#define Ww 640
#define SKIP 8
#define GY 60
#define GX 80
#define P  4800
#define NMAX 8
#define EPSF 1e-6f
#define INLIER 0.9f
#define VTILE 512
#define CBLK  128                       // candidates per vote block
#define NSLICE 4                        // pixel slices per block
#define VTHREADS (CBLK * NSLICE)        // 512
#define VOTE_BX ((P + CBLK - 1) / CBLK) // 38
#define KD (NUM_CLASSES - 1)

// ---------------- device scratch ----------------
static __device__ float    g_u[NMAX][P];
static __device__ float    g_v[NMAX][P];
static __device__ float    g_d[NMAX][P];
static __device__ float4   g_sxyuv[NMAX][P];     // class-sorted (x,y,u,v)
static __device__ float    g_sd[NMAX][P];
static __device__ int      g_segStart[NMAX][11];
static __device__ float    g_counts[NMAX][10];
static __device__ float    g_dsum[NMAX][10][P];
static __device__ unsigned g_bestkey[NMAX][10];  // (cnt<<13)|(8191-c)
static __device__ unsigned g_done[NMAX];

// ================= kernel 1: fused prep + two-level counting sort =================
__global__ void __launch_bounds__(1024, 1)
hv_prep_sort_kernel(const int* __restrict__ label,
                    const float* __restrict__ vp,
                    float* __restrict__ out, int N)
{
    const int n    = blockIdx.x;
    const int tid  = threadIdx.x;
    const int warp = tid >> 5;
    const int lane = tid & 31;
    const unsigned FULL = 0xffffffffu;

    __shared__ int s_lab[P];
    __shared__ int s_cnt[32][10];
    __shared__ int s_off[32][10];

    if (tid < 10) g_bestkey[n][tid] = 0u;
    if (tid == 10) g_done[n] = 0u;
    {
        float* targ = out + (size_t)N * KD * 14 + (size_t)n * KD * 40;
        float* wgt  = out + (size_t)N * KD * 54 + (size_t)n * KD * 40;
        for (int i = tid; i < KD * 40; i += 1024) { targ[i] = 0.0f; wgt[i] = 0.0f; }
    }

    // phase A: stage labels in smem
    const int* lab2d = label + (size_t)n * Hh * Ww;
    for (int p = tid; p < P; p += 1024) {
        int iy = p / GX, ix = p - iy * GX;
        s_lab[p] = lab2d[iy * SKIP * Ww + ix * SKIP];
    }
    __syncthreads();

    // phase B: per-pixel u,v,d -> global
    const float* vpn = vp + (size_t)n * Hh * Ww * (3 * NUM_CLASSES);
    for (int p = tid; p < P; p += 1024) {
        int iy = p / GX, ix = p - iy * GX;
        int l = s_lab[p];
        const float* v3 = vpn + (size_t)(iy * SKIP * Ww + ix * SKIP) * (3 * NUM_CLASSES) + 3 * l;
        float u = v3[0], v = v3[1], w = v3[2];
        float nrm = sqrtf(u * u + v * v) + EPSF;
        g_u[n][p] = u / nrm;
        g_v[n][p] = v / nrm;
        g_d[n][p] = expf(fminf(fmaxf(w, -3.0f), 3.0f));
    }

    // phase C1: per-chunk per-class counts (warp = chunk of 150 pixels)
    int cnt[10];
    #pragma unroll
    for (int k = 0; k < 10; k++) cnt[k] = 0;
    const int cbase = warp * 150;
    #pragma unroll
    for (int s = 0; s < 5; s++) {
        int o = s * 32 + lane;
        int l = (o < 150) ? s_lab[cbase + o] : -1;
        #pragma unroll
        for (int k = 0; k < 10; k++) {
            unsigned m = __ballot_sync(FULL, l == k);
            cnt[k] += __popc(m);
        }
    }
    if (lane == 0) {
        #pragma unroll
        for (int k = 0; k < 10; k++) s_cnt[warp][k] = cnt[k];
    }
    __syncthreads();

    // phase C2: warp 0 — shfl-scan chunk offsets + segment starts
    if (warp == 0) {
        int segrun = 0;
        if (lane == 0) { g_segStart[n][0] = 0; }
        #pragma unroll
        for (int k = 0; k < 10; k++) {
            int v = s_cnt[lane][k];
            int incl = v;
            #pragma unroll
            for (int d = 1; d < 32; d <<= 1) {
                int t = __shfl_up_sync(FULL, incl, d);
                if (lane >= d) incl += t;
            }
            int excl  = incl - v;
            int total = __shfl_sync(FULL, incl, 31);
            if (k >= 1) {
                s_off[lane][k] = segrun + excl;
                if (lane == 0) g_segStart[n][k] = segrun;
                segrun += total;
            }
            if (lane == 0) g_counts[n][k] = (float)total;
        }
        if (lane == 0) g_segStart[n][10] = segrun;
    }
    __syncthreads();

    // phase C3: parallel stable scatter (warp = chunk)
    int off[10];
    #pragma unroll
    for (int k = 1; k < 10; k++) off[k] = s_off[warp][k];
    #pragma unroll
    for (int s = 0; s < 5; s++) {
        int o = s * 32 + lane;
        int j = cbase + o;
        bool valid = (o < 150);
        int l = valid ? s_lab[j] : -1;
        float u = 0.f, v = 0.f, d = 0.f, x = 0.f, y = 0.f;
        if (valid && l > 0) {
            u = g_u[n][j]; v = g_v[n][j]; d = g_d[n][j];
            int iy = j / GX, ix = j - iy * GX;
            x = (float)(ix * SKIP);
            y = (float)(iy * SKIP);
        }
        #pragma unroll
        for (int k = 1; k < 10; k++) {
            unsigned m = __ballot_sync(FULL, l == k);
            if (l == k) {
                int pos = off[k] + __popc(m & ((1u << lane) - 1u));
                g_sxyuv[n][pos] = make_float4(x, y, u, v);
                g_sd[n][pos]    = d;
            }
            off[k] += __popc(m);
        }
    }
}

// ================= kernel 2: voting (sliced) + fused argmax + epilogue =================
__global__ void __launch_bounds__(VTHREADS)
hv_vote_kernel(const float* __restrict__ extents,
               const float* __restrict__ meta,
               float* __restrict__ out, int N)
{
    const int n = blockIdx.z;
    const int k = blockIdx.y + 1;
    const int tid   = threadIdx.x;
    const int cl    = tid & (CBLK - 1);   // candidate within block
    const int slice = tid >> 7;           // 0..3
    const int c     = blockIdx.x * CBLK + cl;

    __shared__ float4   sxy[VTILE];
    __shared__ float    sdd[VTILE];
    __shared__ int      s_pcnt[NSLICE][CBLK];
    __shared__ float    s_pds[NSLICE][CBLK];
    __shared__ unsigned skey[CBLK];
    __shared__ int      s_last;

    const int beg = g_segStart[n][k];
    const int end = g_segStart[n][k + 1];

    float fcx = 0.f, fcy = 0.f;
    if (c < P) {
        int iy = c / GX, ix = c - iy * GX;
        fcx = (float)(ix * SKIP);
        fcy = (float)(iy * SKIP);
    }

    int   cnt = 0;
    float ds  = 0.0f;

    for (int base = beg; base < end; base += VTILE) {
        int m = end - base;
        if (m > VTILE) m = VTILE;
        for (int j = tid; j < m; j += VTHREADS) {
            sxy[j] = g_sxyuv[n][base + j];
            sdd[j] = g_sd[n][base + j];
        }
        __syncthreads();
        if (c < P) {
            for (int j = slice; j < m; j += NSLICE) {
                float4 t = sxy[j];
                float dx  = fcx - t.x;
                float dy  = fcy - t.y;
                float s   = fmaf(dx, dx, dy * dy);
                float dot = fmaf(t.z, dx, t.w * dy);
                float d2  = dot * dot;
                float t81 = 0.81f * s;
                float gd  = d2 - t81;
                bool inl;
                if (fabsf(gd) < 1e-5f * s) {
                    // exact IEEE path (same formula as reference)
                    float rd = sqrtf(s) + EPSF;
                    inl = (dot / rd) > INLIER;
                } else {
                    inl = (dot > 0.0f) && (gd > 0.0f);
                }
                if (inl) { cnt++; ds += sdd[j]; }
            }
        }
        __syncthreads();
    }

    // deterministic fixed-order slice reduction
    s_pcnt[slice][cl] = cnt;
    s_pds[slice][cl]  = ds;
    __syncthreads();

    if (slice == 0) {
        int   tc = s_pcnt[0][cl];
        float td = s_pds[0][cl];
        #pragma unroll
        for (int q = 1; q < NSLICE; q++) {
            tc += s_pcnt[q][cl];
            td += s_pds[q][cl];
        }
        unsigned key = 0u;
        if (c < P) {
            g_dsum[n][k][c] = td;
            key = (((unsigned)tc) << 13) | (unsigned)(8191 - c);
        }
        skey[cl] = key;
    }
    __syncthreads();

    // block max over 128 candidate keys
    for (int s = CBLK / 2; s > 0; s >>= 1) {
        if (tid < s) {
            unsigned o = skey[tid + s];
            if (o > skey[tid]) skey[tid] = o;
        }
        __syncthreads();
    }
    if (tid == 0) {
        atomicMax(&g_bestkey[n][k], skey[0]);
        __threadfence();
        unsigned t = atomicAdd(&g_done[n], 1u);
        s_last = (t == (unsigned)(VOTE_BX * KD - 1)) ? 1 : 0;
    }
    __syncthreads();

    // last block of this n: epilogue
    if (s_last && tid < KD) {
        __threadfence();
        const int kk = tid + 1;
        unsigned bkey = g_bestkey[n][kk];
        float votes = (float)(bkey >> 13);
        int   best  = 8191 - (int)(bkey & 8191u);

        float davg = g_dsum[n][kk][best] / fmaxf(votes, 1.0f);
        int iy = best / GX, ix = best - iy * GX;
        float cx = (float)(ix * SKIP);
        float cy = (float)(iy * SKIP);
        float cntk = g_counts[n][kk];

        bool valid = (votes > 20.0f) && (votes > 0.1f * cntk)
                     && (cntk * (float)(SKIP * SKIP) > 500.0f);

        const float* mt = meta + (size_t)n * 9;
        float fx = mt[0], fy = mt[4], ppx = mt[2], ppy = mt[5];

        float e0 = extents[kk * 3 + 0];
        float e1 = extents[kk * 3 + 1];
        float e2 = extents[kk * 3 + 2];
        float diam = sqrtf(e0 * e0 + e1 * e1 + e2 * e2) + EPSF;

        float hx = 0.5f * diam * fx / fmaxf(davg, EPSF);
        float hy = 0.5f * diam * fy / fmaxf(davg, EPSF);
        float score = valid ? votes : 0.0f;

        float* b = out + ((size_t)n * KD + (kk - 1)) * 7;
        b[0] = (float)n;
        b[1] = (float)kk;
        b[2] = cx - hx;
        b[3] = cy - hy;
        b[4] = cx + hx;
        b[5] = cy + hy;
        b[6] = score;

        float* ps = out + (size_t)N * KD * 7 + ((size_t)n * KD + (kk - 1)) * 7;
        ps[0] = 1.0f; ps[1] = 0.0f; ps[2] = 0.0f; ps[3] = 0.0f;
        ps[4] = (cx - ppx) * davg / fx;
        ps[5] = (cy - ppy) * davg / fy;
        ps[6] = davg;

        out[(size_t)N * KD * 94 + (size_t)n * KD + (kk - 1)] = (float)n;
    }
}

// ---------------- launch ----------------
extern "C" void kernel_launch(void* const* d_in, const int* in_sizes, int n_in,
                              void* d_out, int out_size)
{
    const int*   label   = (const int*)d_in[0];
    const float* vp      = (const float*)d_in[1];
    const float* extents = (const float*)d_in[2];
    const float* meta    = (const float*)d_in[4];
    float* out = (float*)d_out;

    int N = in_sizes[4] / 9;
    if (N < 1) N = 1;
    if (N > NMAX) N = NMAX;

    hv_prep_sort_kernel<<<N, 1024>>>(label, vp, out, N);

    dim3 gv(VOTE_BX, KD, N);
    hv_vote_kernel<<<gv, VTHREADS>>>(extents, meta, out, N);
}

// round 6
// speedup vs baseline: 3.9529x; 1.1568x over previous
#include <cuda_runtime.h>
#include <math.h>

#define NUM_CLASSES 10
#define Hh 480
#define Ww 640
#define SKIP 8
#define GY 60
#define GX 80
#define P  4800
#define NMAX 8
#define EPSF 1e-6f
#define INLIER 0.9f
#define VTILE 512
#define CBLK  128                        // candidates per vote block
#define CLANES 64                        // candidate lanes (2 candidates each)
#define NSLICE 4
#define VTHREADS 256
#define VOTE_BX ((P + CBLK - 1) / CBLK)  // 38
#define KD (NUM_CLASSES - 1)

// ---------------- device scratch ----------------
static __device__ int      g_sidx[NMAX][P];       // sorted pos -> pixel index
static __device__ int      g_sklass[NMAX][P];     // sorted pos -> class
static __device__ float4   g_sxyuv[NMAX][P];      // sorted (x,y,u,v)
static __device__ float    g_sd[NMAX][P];         // sorted d
static __device__ int      g_segStart[NMAX][11];
static __device__ float    g_counts[NMAX][10];
static __device__ unsigned g_bestkey[NMAX][10];   // (cnt<<13)|(8191-c)

// shared inlier predicate: fast quadratic test + exact IEEE fallback in guard band.
// Must be used identically by vote and epilogue so inlier sets match.
__device__ __forceinline__ bool hv_inlier(float fcx, float fcy, float4 t)
{
    float dx   = fcx - t.x;
    float dy   = fcy - t.y;
    float s    = fmaf(dx, dx, dy * dy);          // exact (grid-integer coords)
    float dot  = fmaf(t.z, dx, t.w * dy);
    float dotp = fmaxf(dot, 0.0f);
    float t81  = 0.81f * s;
    float gd   = fmaf(dotp, dotp, -t81);
    if (fabsf(gd) < 1e-5f * s) {
        float rd = sqrtf(s) + EPSF;              // exact reference formula
        return (dot / rd) > INLIER;
    }
    return gd > 0.0f;
}

// ================= kernel A: labels-only counting sort (1 block/n) =================
__global__ void __launch_bounds__(1024, 1)
hv_sort_kernel(const int* __restrict__ label)
{
    const int n    = blockIdx.x;
    const int tid  = threadIdx.x;
    const int warp = tid >> 5;
    const int lane = tid & 31;
    const unsigned FULL = 0xffffffffu;

    __shared__ int s_lab[P];
    __shared__ int s_cnt[32][10];
    __shared__ int s_off[32][10];

    if (tid < 10) g_bestkey[n][tid] = 0u;

    const int* lab2d = label + (size_t)n * Hh * Ww;
    for (int p = tid; p < P; p += 1024) {
        int iy = p / GX, ix = p - iy * GX;
        s_lab[p] = lab2d[iy * SKIP * Ww + ix * SKIP];
    }
    __syncthreads();

    // per-chunk per-class counts (warp = chunk of 150 pixels)
    int cnt[10];
    #pragma unroll
    for (int k = 0; k < 10; k++) cnt[k] = 0;
    const int cbase = warp * 150;
    #pragma unroll
    for (int s = 0; s < 5; s++) {
        int o = s * 32 + lane;
        int l = (o < 150) ? s_lab[cbase + o] : -1;
        #pragma unroll
        for (int k = 0; k < 10; k++) {
            unsigned m = __ballot_sync(FULL, l == k);
            cnt[k] += __popc(m);
        }
    }
    if (lane == 0) {
        #pragma unroll
        for (int k = 0; k < 10; k++) s_cnt[warp][k] = cnt[k];
    }
    __syncthreads();

    // warp 0: shfl-scan chunk offsets + segment starts
    if (warp == 0) {
        int segrun = 0;
        if (lane == 0) g_segStart[n][0] = 0;
        #pragma unroll
        for (int k = 0; k < 10; k++) {
            int v = s_cnt[lane][k];
            int incl = v;
            #pragma unroll
            for (int d = 1; d < 32; d <<= 1) {
                int t = __shfl_up_sync(FULL, incl, d);
                if (lane >= d) incl += t;
            }
            int excl  = incl - v;
            int total = __shfl_sync(FULL, incl, 31);
            if (k >= 1) {
                s_off[lane][k] = segrun + excl;
                if (lane == 0) g_segStart[n][k] = segrun;
                segrun += total;
            }
            if (lane == 0) g_counts[n][k] = (float)total;
        }
        if (lane == 0) g_segStart[n][10] = segrun;
    }
    __syncthreads();

    // parallel stable scatter of indices (warp = chunk)
    int off[10];
    #pragma unroll
    for (int k = 1; k < 10; k++) off[k] = s_off[warp][k];
    #pragma unroll
    for (int s = 0; s < 5; s++) {
        int o = s * 32 + lane;
        int j = cbase + o;
        int l = (o < 150) ? s_lab[j] : -1;
        #pragma unroll
        for (int k = 1; k < 10; k++) {
            unsigned m = __ballot_sync(FULL, l == k);
            if (l == k) {
                int pos = off[k] + __popc(m & ((1u << lane) - 1u));
                g_sidx[n][pos]   = j;
                g_sklass[n][pos] = k;
            }
            off[k] += __popc(m);
        }
    }
}

// ================= kernel B: parallel gather/compute into sorted order =================
__global__ void hv_gather_kernel(const float* __restrict__ vp)
{
    const int n   = blockIdx.y;
    const int pos = blockIdx.x * blockDim.x + threadIdx.x;
    if (pos >= g_segStart[n][10]) return;

    int p = g_sidx[n][pos];
    int l = g_sklass[n][pos];
    int iy = p / GX, ix = p - iy * GX;

    const float* v3 = vp + (size_t)n * Hh * Ww * (3 * NUM_CLASSES)
                         + (size_t)(iy * SKIP * Ww + ix * SKIP) * (3 * NUM_CLASSES) + 3 * l;
    float u = v3[0], v = v3[1], w = v3[2];
    float nrm = sqrtf(u * u + v * v) + EPSF;

    g_sxyuv[n][pos] = make_float4((float)(ix * SKIP), (float)(iy * SKIP), u / nrm, v / nrm);
    g_sd[n][pos]    = expf(fminf(fmaxf(w, -3.0f), 3.0f));
}

// ================= kernel C: voting (counts only) + fused argmax =================
__global__ void __launch_bounds__(VTHREADS)
hv_vote_kernel()
{
    const int n = blockIdx.z;
    const int k = blockIdx.y + 1;
    const int tid   = threadIdx.x;
    const int cl    = tid & (CLANES - 1);
    const int slice = tid >> 6;                  // 0..3
    const int cb    = blockIdx.x * CBLK;
    const int c0 = cb + cl;
    const int c1 = cb + CLANES + cl;

    __shared__ float4   sxy[VTILE];
    __shared__ int      s_pcnt[NSLICE][CLANES][2];
    __shared__ unsigned skey[CLANES];

    const int beg = g_segStart[n][k];
    const int end = g_segStart[n][k + 1];

    float fcx0 = 0.f, fcy0 = 0.f, fcx1 = 0.f, fcy1 = 0.f;
    const bool v0 = (c0 < P), v1 = (c1 < P);
    if (v0) { int iy = c0 / GX, ix = c0 - iy * GX; fcx0 = (float)(ix * SKIP); fcy0 = (float)(iy * SKIP); }
    if (v1) { int iy = c1 / GX, ix = c1 - iy * GX; fcx1 = (float)(ix * SKIP); fcy1 = (float)(iy * SKIP); }

    int cnt0 = 0, cnt1 = 0;

    for (int base = beg; base < end; base += VTILE) {
        int m = end - base;
        if (m > VTILE) m = VTILE;
        for (int j = tid; j < m; j += VTHREADS)
            sxy[j] = g_sxyuv[n][base + j];
        __syncthreads();
        for (int j = slice; j < m; j += NSLICE) {
            float4 t = sxy[j];
            if (hv_inlier(fcx0, fcy0, t)) cnt0++;
            if (hv_inlier(fcx1, fcy1, t)) cnt1++;
        }
        __syncthreads();
    }

    s_pcnt[slice][cl][0] = cnt0;
    s_pcnt[slice][cl][1] = cnt1;
    __syncthreads();

    if (slice == 0) {
        int t0 = 0, t1 = 0;
        #pragma unroll
        for (int q = 0; q < NSLICE; q++) { t0 += s_pcnt[q][cl][0]; t1 += s_pcnt[q][cl][1]; }
        unsigned k0 = v0 ? ((((unsigned)t0) << 13) | (unsigned)(8191 - c0)) : 0u;
        unsigned k1 = v1 ? ((((unsigned)t1) << 13) | (unsigned)(8191 - c1)) : 0u;
        skey[cl] = (k0 > k1) ? k0 : k1;
    }
    __syncthreads();

    for (int s = CLANES / 2; s > 0; s >>= 1) {
        if (tid < s) {
            unsigned o = skey[tid + s];
            if (o > skey[tid]) skey[tid] = o;
        }
        __syncthreads();
    }
    if (tid == 0)
        atomicMax(&g_bestkey[n][k], skey[0]);
}

// ================= kernel D: winner dsum + epilogue + zero train outputs =================
__global__ void __launch_bounds__(256)
hv_final_kernel(const float* __restrict__ extents,
                const float* __restrict__ meta,
                float* __restrict__ out, int N)
{
    const int k   = blockIdx.x + 1;
    const int n   = blockIdx.y;
    const int tid = threadIdx.x;

    // zero train-only slices for this (n,k)
    {
        float* targ = out + (size_t)N * KD * 14 + ((size_t)n * KD + (k - 1)) * 40;
        float* wgt  = out + (size_t)N * KD * 54 + ((size_t)n * KD + (k - 1)) * 40;
        if (tid < 40) { targ[tid] = 0.0f; wgt[tid] = 0.0f; }
    }

    unsigned bkey = g_bestkey[n][k];
    float votes = (float)(bkey >> 13);
    int   best  = 8191 - (int)(bkey & 8191u);
    int biy = best / GX, bix = best - biy * GX;
    float cx = (float)(bix * SKIP);
    float cy = (float)(biy * SKIP);

    const int beg = g_segStart[n][k];
    const int end = g_segStart[n][k + 1];

    // recompute dsum at the winning candidate (identical predicate as vote)
    float ds = 0.0f;
    for (int j = beg + tid; j < end; j += 256) {
        float4 t = g_sxyuv[n][j];
        if (hv_inlier(cx, cy, t)) ds += g_sd[n][j];
    }
    __shared__ float rds[256];
    rds[tid] = ds;
    __syncthreads();
    for (int s = 128; s > 0; s >>= 1) {
        if (tid < s) rds[tid] += rds[tid + s];
        __syncthreads();
    }

    if (tid == 0) {
        float dsum = rds[0];
        float davg = dsum / fmaxf(votes, 1.0f);
        float cntk = g_counts[n][k];

        bool valid = (votes > 20.0f) && (votes > 0.1f * cntk)
                     && (cntk * (float)(SKIP * SKIP) > 500.0f);

        const float* mt = meta + (size_t)n * 9;
        float fx = mt[0], fy = mt[4], ppx = mt[2], ppy = mt[5];

        float e0 = extents[k * 3 + 0];
        float e1 = extents[k * 3 + 1];
        float e2 = extents[k * 3 + 2];
        float diam = sqrtf(e0 * e0 + e1 * e1 + e2 * e2) + EPSF;

        float hx = 0.5f * diam * fx / fmaxf(davg, EPSF);
        float hy = 0.5f * diam * fy / fmaxf(davg, EPSF);
        float score = valid ? votes : 0.0f;

        float* b = out + ((size_t)n * KD + (k - 1)) * 7;
        b[0] = (float)n;
        b[1] = (float)k;
        b[2] = cx - hx;
        b[3] = cy - hy;
        b[4] = cx + hx;
        b[5] = cy + hy;
        b[6] = score;

        float* ps = out + (size_t)N * KD * 7 + ((size_t)n * KD + (k - 1)) * 7;
        ps[0] = 1.0f; ps[1] = 0.0f; ps[2] = 0.0f; ps[3] = 0.0f;
        ps[4] = (cx - ppx) * davg / fx;
        ps[5] = (cy - ppy) * davg / fy;
        ps[6] = davg;

        out[(size_t)N * KD * 94 + (size_t)n * KD + (k - 1)] = (float)n;
    }
}

// ---------------- launch ----------------
extern "C" void kernel_launch(void* const* d_in, const int* in_sizes, int n_in,
                              void* d_out, int out_size)
{
    const int*   label   = (const int*)d_in[0];
    const float* vp      = (const float*)d_in[1];
    const float* extents = (const float*)d_in[2];
    const float* meta    = (const float*)d_in[4];
    float* out = (float*)d_out;

    int N = in_sizes[4] / 9;
    if (N < 1) N = 1;
    if (N > NMAX) N = NMAX;

    hv_sort_kernel<<<N, 1024>>>(label);

    dim3 gb((P + 255) / 256, N);
    hv_gather_kernel<<<gb, 256>>>(vp);

    dim3 gv(VOTE_BX, KD, N);
    hv_vote_kernel<<<gv, VTHREADS>>>();

    dim3 gf(KD, N);
    hv_final_kernel<<<gf, 256>>>(extents, meta, out, N);
}